// round 9
// baseline (speedup 1.0000x reference)
#include <cuda_runtime.h>
#include <math.h>

#define BATCH 8
#define CHAN 128
#define PLANE 65536          // D*H*W = 4*128*128
#define NBC (BATCH * CHAN)   // 1024

__device__ float g_max[NBC];
__device__ float g_hid[NBC];                       // hidden layer h[b][o]
__device__ volatile unsigned int g_flag[BATCH];    // h[b] published?

// ---------------------------------------------------------------------------
// Kernel 1: per-(b,c) global max (verified ~40-42us, ~84% of HBM spec).
// Block 0 also resets the publish flags for this replay (stream order
// guarantees the previous gate_scale finished).
// ---------------------------------------------------------------------------
__global__ __launch_bounds__(512) void reduce_max_kernel(const float* __restrict__ x) {
    const int bc = blockIdx.x;
    const int tid = threadIdx.x;
    if (bc == 0 && tid < BATCH) g_flag[tid] = 0u;

    const float4* p = reinterpret_cast<const float4*>(x) + (size_t)bc * (PLANE / 4);

    float m0 = -INFINITY, m1 = -INFINITY;
    #pragma unroll 4
    for (int i = tid; i < PLANE / 4; i += 1024) {
        float4 a = __ldcs(p + i);
        float4 b = __ldcs(p + i + 512);
        m0 = fmaxf(m0, fmaxf(fmaxf(a.x, a.y), fmaxf(a.z, a.w)));
        m1 = fmaxf(m1, fmaxf(fmaxf(b.x, b.y), fmaxf(b.z, b.w)));
    }
    float m = fmaxf(m0, m1);

    #pragma unroll
    for (int off = 16; off > 0; off >>= 1)
        m = fmaxf(m, __shfl_xor_sync(0xffffffffu, m, off));

    __shared__ float sm[16];
    if ((tid & 31) == 0) sm[tid >> 5] = m;
    __syncthreads();
    if (tid < 16) {
        m = sm[tid];
        #pragma unroll
        for (int off = 8; off > 0; off >>= 1)
            m = fmaxf(m, __shfl_xor_sync(0x0000ffffu, m, off));
        if (tid == 0) g_max[bc] = m;
    }
}

// ---------------------------------------------------------------------------
// Kernel 2: fused hidden + gate + streaming scale.
// 8192 blocks (8 per plane) x 256 threads x 8 float4 (verified structure).
//
// Blocks 0..7: first compute h[b,:] for batch b=blockIdx.x (128 threads, one
// hidden unit each), publish via threadfence + flag. These 8 blocks are in
// wave 1 (first 148 blocks -> distinct SMs), so every polling block makes
// progress. All blocks issue their 8 x-loads BEFORE polling, hiding the
// hidden-GEMV latency behind the load stream.
// ---------------------------------------------------------------------------
__global__ __launch_bounds__(256, 6) void gate_scale_kernel(const float* __restrict__ x,
                                                            const float* __restrict__ w1,
                                                            const float* __restrict__ b1,
                                                            const float* __restrict__ w2,
                                                            const float* __restrict__ b2,
                                                            float* __restrict__ out) {
    const int tid = threadIdx.x;
    const int bc  = blockIdx.x >> 3;        // 8 blocks per plane
    const int b   = bc >> 7;
    const int c   = bc & 127;

    __shared__ float s_gate;

    // --- producer blocks: hidden layer for one batch ---
    if (blockIdx.x < BATCH) {
        const int hb = blockIdx.x;
        if (tid < CHAN) {
            __shared__ float gp[CHAN];
            gp[tid] = __ldcg(&g_max[hb * CHAN + tid]);
            __syncwarp();        // gp written by the same 4 warps that read it
            __syncthreads();
            float acc = __ldg(&b1[tid]);
            const float4* wrow = reinterpret_cast<const float4*>(w1 + (size_t)tid * CHAN);
            #pragma unroll 8
            for (int q = 0; q < CHAN / 4; q++) {
                float4 w = __ldg(wrow + q);
                const int k = q * 4;
                acc = fmaf(gp[k],     w.x, acc);
                acc = fmaf(gp[k + 1], w.y, acc);
                acc = fmaf(gp[k + 2], w.z, acc);
                acc = fmaf(gp[k + 3], w.w, acc);
            }
            g_hid[hb * CHAN + tid] = fmaxf(acc, 0.0f);
        } else {
            __syncthreads();
        }
        __syncthreads();
        if (tid == 0) {
            __threadfence();
            g_flag[hb] = 1u;
        }
    }

    // --- everyone: issue the 8 independent x loads first ---
    const size_t base = (size_t)blockIdx.x * 2048 + tid;
    const float4* xp = reinterpret_cast<const float4*>(x);
    float4* op = reinterpret_cast<float4*>(out);

    float4 v[8];
    #pragma unroll
    for (int k = 0; k < 8; k++)
        v[k] = __ldcs(xp + base + (size_t)k * 256);

    // --- warp 0: wait for h[b], compute gate ---
    if (tid < 32) {
        while (g_flag[b] == 0u) { }
        __threadfence();
        const float4 w = __ldg(reinterpret_cast<const float4*>(w2 + (size_t)c * CHAN) + tid);
        const float4 h = __ldcg(reinterpret_cast<const float4*>(g_hid + (size_t)b * CHAN) + tid);
        float s = h.x * w.x + h.y * w.y + h.z * w.z + h.w * w.w;
        #pragma unroll
        for (int off = 16; off > 0; off >>= 1)
            s += __shfl_xor_sync(0xffffffffu, s, off);
        if (tid == 0)
            s_gate = 1.0f / (1.0f + expf(-(s + __ldg(&b2[c]))));
    }
    __syncthreads();
    const float g = s_gate;

    #pragma unroll
    for (int k = 0; k < 8; k++) {
        v[k].x *= g; v[k].y *= g; v[k].z *= g; v[k].w *= g;
        __stcs(op + base + (size_t)k * 256, v[k]);
    }
}

// ---------------------------------------------------------------------------
extern "C" void kernel_launch(void* const* d_in, const int* in_sizes, int n_in,
                              void* d_out, int out_size) {
    const float* x  = (const float*)d_in[0];
    const float* w1 = (const float*)d_in[1];
    const float* b1 = (const float*)d_in[2];
    const float* w2 = (const float*)d_in[3];
    const float* b2 = (const float*)d_in[4];
    float* out = (float*)d_out;

    reduce_max_kernel<<<NBC, 512>>>(x);
    gate_scale_kernel<<<8192, 256>>>(x, w1, b1, w2, b2, out);
}

// round 11
// speedup vs baseline: 1.0083x; 1.0083x over previous
#include <cuda_runtime.h>
#include <math.h>

#define BATCH 8
#define CHAN 128
#define PLANE 65536          // D*H*W = 4*128*128
#define NBC (BATCH * CHAN)   // 1024

__device__ float g_max[NBC];
__device__ float g_hid[NBC];                       // hidden layer h[b][o]
__device__ volatile unsigned int g_flag[BATCH];    // h[b] published?

// ---------------------------------------------------------------------------
// Kernel 1: per-(b,c) global max (verified ~40-42us, ~84% of HBM spec).
// Block 0 resets publish flags for this replay (stream order guarantees the
// previous gate_scale is done).
// ---------------------------------------------------------------------------
__global__ __launch_bounds__(512) void reduce_max_kernel(const float* __restrict__ x) {
    const int bc = blockIdx.x;
    const int tid = threadIdx.x;
    if (bc == 0 && tid < BATCH) g_flag[tid] = 0u;

    const float4* p = reinterpret_cast<const float4*>(x) + (size_t)bc * (PLANE / 4);

    float m0 = -INFINITY, m1 = -INFINITY;
    #pragma unroll 4
    for (int i = tid; i < PLANE / 4; i += 1024) {
        float4 a = __ldcs(p + i);
        float4 b = __ldcs(p + i + 512);
        m0 = fmaxf(m0, fmaxf(fmaxf(a.x, a.y), fmaxf(a.z, a.w)));
        m1 = fmaxf(m1, fmaxf(fmaxf(b.x, b.y), fmaxf(b.z, b.w)));
    }
    float m = fmaxf(m0, m1);

    #pragma unroll
    for (int off = 16; off > 0; off >>= 1)
        m = fmaxf(m, __shfl_xor_sync(0xffffffffu, m, off));

    __shared__ float sm[16];
    if ((tid & 31) == 0) sm[tid >> 5] = m;
    __syncthreads();
    if (tid < 16) {
        m = sm[tid];
        #pragma unroll
        for (int off = 8; off > 0; off >>= 1)
            m = fmaxf(m, __shfl_xor_sync(0x0000ffffu, m, off));
        if (tid == 0) g_max[bc] = m;
    }
}

// ---------------------------------------------------------------------------
// Kernel 2: fused hidden + gate + streaming scale, per-warp sync-free.
// 8192 blocks (8 per plane) x 256 threads x 8 float4 (verified structure).
//
// Blocks 0..7 (wave-1 resident, distinct SMs): compute h[b,:] for batch
// b = blockIdx.x, fence, set flag; then stream like everyone else.
// Consumers: issue 8 x-loads, then EACH WARP independently polls flag[b],
// fences, and computes the gate redundantly (32-lane float4 dot + shuffle;
// w2 row and h row are L1/L2-hot). No __syncthreads in the streaming path:
// each warp's stores go as soon as its own gate is ready.
// ---------------------------------------------------------------------------
__global__ __launch_bounds__(256) void gate_scale_kernel(const float* __restrict__ x,
                                                         const float* __restrict__ w1,
                                                         const float* __restrict__ b1,
                                                         const float* __restrict__ w2,
                                                         const float* __restrict__ b2,
                                                         float* __restrict__ out) {
    const int tid  = threadIdx.x;
    const int lane = tid & 31;
    const int bc   = blockIdx.x >> 3;       // 8 blocks per plane
    const int b    = bc >> 7;
    const int c    = bc & 127;

    __shared__ float gp[CHAN];

    // --- producer blocks: hidden layer for one batch ---
    if (blockIdx.x < BATCH) {
        const int hb = blockIdx.x;
        if (tid < CHAN)
            gp[tid] = __ldcg(&g_max[hb * CHAN + tid]);
        __syncthreads();
        if (tid < CHAN) {
            float acc = __ldg(&b1[tid]);
            const float4* wrow = reinterpret_cast<const float4*>(w1 + (size_t)tid * CHAN);
            #pragma unroll 8
            for (int q = 0; q < CHAN / 4; q++) {
                float4 w = __ldg(wrow + q);
                const int k = q * 4;
                acc = fmaf(gp[k],     w.x, acc);
                acc = fmaf(gp[k + 1], w.y, acc);
                acc = fmaf(gp[k + 2], w.z, acc);
                acc = fmaf(gp[k + 3], w.w, acc);
            }
            g_hid[hb * CHAN + tid] = fmaxf(acc, 0.0f);
        }
        __syncthreads();
        if (tid == 0) {
            __threadfence();
            g_flag[hb] = 1u;
        }
    }

    // --- everyone: issue the 8 independent x loads first ---
    const size_t base = (size_t)blockIdx.x * 2048 + tid;
    const float4* xp = reinterpret_cast<const float4*>(x);
    float4* op = reinterpret_cast<float4*>(out);

    float4 v[8];
    #pragma unroll
    for (int k = 0; k < 8; k++)
        v[k] = __ldcs(xp + base + (size_t)k * 256);

    // --- per-warp: wait for h[b], compute gate redundantly (no block sync) ---
    while (g_flag[b] == 0u)
        __nanosleep(100);
    __threadfence();

    const float4 w = __ldg(reinterpret_cast<const float4*>(w2 + (size_t)c * CHAN) + lane);
    const float4 h = __ldcg(reinterpret_cast<const float4*>(g_hid + (size_t)b * CHAN) + lane);
    float s = h.x * w.x + h.y * w.y + h.z * w.z + h.w * w.w;
    #pragma unroll
    for (int off = 16; off > 0; off >>= 1)
        s += __shfl_xor_sync(0xffffffffu, s, off);
    const float g = 1.0f / (1.0f + expf(-(s + __ldg(&b2[c]))));

    #pragma unroll
    for (int k = 0; k < 8; k++) {
        v[k].x *= g; v[k].y *= g; v[k].z *= g; v[k].w *= g;
        __stcs(op + base + (size_t)k * 256, v[k]);
    }
}

// ---------------------------------------------------------------------------
extern "C" void kernel_launch(void* const* d_in, const int* in_sizes, int n_in,
                              void* d_out, int out_size) {
    const float* x  = (const float*)d_in[0];
    const float* w1 = (const float*)d_in[1];
    const float* b1 = (const float*)d_in[2];
    const float* w2 = (const float*)d_in[3];
    const float* b2 = (const float*)d_in[4];
    float* out = (float*)d_out;

    reduce_max_kernel<<<NBC, 512>>>(x);
    gate_scale_kernel<<<8192, 256>>>(x, w1, b1, w2, b2, out);
}

// round 12
// speedup vs baseline: 1.0174x; 1.0091x over previous
#include <cuda_runtime.h>
#include <math.h>

#define BATCH 8
#define CHAN 128
#define PLANE 65536          // D*H*W = 4*128*128
#define NBC (BATCH * CHAN)   // 1024

__device__ float g_max[NBC];
__device__ float g_gate[NBC];

// ---------------------------------------------------------------------------
// Kernel 1: per-(b,c) global max (verified ~40-42us, ~84% of HBM spec).
// ---------------------------------------------------------------------------
__global__ __launch_bounds__(512) void reduce_max_kernel(const float* __restrict__ x) {
    const int bc = blockIdx.x;
    const int tid = threadIdx.x;
    const float4* p = reinterpret_cast<const float4*>(x) + (size_t)bc * (PLANE / 4);

    float m0 = -INFINITY, m1 = -INFINITY;
    #pragma unroll 4
    for (int i = tid; i < PLANE / 4; i += 1024) {
        float4 a = __ldcs(p + i);
        float4 b = __ldcs(p + i + 512);
        m0 = fmaxf(m0, fmaxf(fmaxf(a.x, a.y), fmaxf(a.z, a.w)));
        m1 = fmaxf(m1, fmaxf(fmaxf(b.x, b.y), fmaxf(b.z, b.w)));
    }
    float m = fmaxf(m0, m1);

    #pragma unroll
    for (int off = 16; off > 0; off >>= 1)
        m = fmaxf(m, __shfl_xor_sync(0xffffffffu, m, off));

    __shared__ float sm[16];
    if ((tid & 31) == 0) sm[tid >> 5] = m;
    __syncthreads();
    if (tid < 16) {
        m = sm[tid];
        #pragma unroll
        for (int off = 8; off > 0; off >>= 1)
            m = fmaxf(m, __shfl_xor_sync(0x0000ffffu, m, off));
        if (tid == 0) g_max[bc] = m;
    }
}

// ---------------------------------------------------------------------------
// Kernel 2: full MLP gate, 8 blocks (one per batch) x 128 threads.
// Phase 1: h[o] = relu(b1[o] + dot(w1[o,:], gp))   (one hidden unit/thread)
// Phase 2: gate[b][o] = sigmoid(b2[o] + dot(w2[o,:], h))
// Weight rows loaded as float4 (high MLP); w1/w2 shared across 8 blocks in L2.
// ---------------------------------------------------------------------------
__global__ __launch_bounds__(128) void mlp_gate_kernel(const float* __restrict__ w1,
                                                       const float* __restrict__ b1,
                                                       const float* __restrict__ w2,
                                                       const float* __restrict__ b2) {
    const int b = blockIdx.x;
    const int o = threadIdx.x;

    __shared__ float gp[CHAN];
    __shared__ float hs[CHAN];
    gp[o] = g_max[b * CHAN + o];
    __syncthreads();

    {
        float acc = __ldg(&b1[o]);
        const float4* wrow = reinterpret_cast<const float4*>(w1 + (size_t)o * CHAN);
        #pragma unroll 8
        for (int q = 0; q < CHAN / 4; q++) {
            float4 w = __ldg(wrow + q);
            const int k = q * 4;
            acc = fmaf(gp[k],     w.x, acc);
            acc = fmaf(gp[k + 1], w.y, acc);
            acc = fmaf(gp[k + 2], w.z, acc);
            acc = fmaf(gp[k + 3], w.w, acc);
        }
        hs[o] = fmaxf(acc, 0.0f);
    }
    __syncthreads();

    {
        float acc = __ldg(&b2[o]);
        const float4* wrow = reinterpret_cast<const float4*>(w2 + (size_t)o * CHAN);
        #pragma unroll 8
        for (int q = 0; q < CHAN / 4; q++) {
            float4 w = __ldg(wrow + q);
            const int k = q * 4;
            acc = fmaf(hs[k],     w.x, acc);
            acc = fmaf(hs[k + 1], w.y, acc);
            acc = fmaf(hs[k + 2], w.z, acc);
            acc = fmaf(hs[k + 3], w.w, acc);
        }
        g_gate[b * CHAN + o] = 1.0f / (1.0f + expf(-acc));
    }
}

// ---------------------------------------------------------------------------
// Kernel 3: out = x * gate[bc].  EXACT verified R4 kernel (75.5us, 80% spec).
// 8192 blocks (8 per plane) x 256 threads x 8 front-batched float4.
// ---------------------------------------------------------------------------
__global__ __launch_bounds__(256) void scale_kernel(const float* __restrict__ x,
                                                    float* __restrict__ out) {
    const float g = g_gate[blockIdx.x >> 3];     // 8 blocks per (b,c) plane
    const size_t base = (size_t)blockIdx.x * 2048 + threadIdx.x;
    const float4* xp = reinterpret_cast<const float4*>(x);
    float4* op = reinterpret_cast<float4*>(out);

    float4 v[8];
    #pragma unroll
    for (int k = 0; k < 8; k++)
        v[k] = __ldcs(xp + base + (size_t)k * 256);

    #pragma unroll
    for (int k = 0; k < 8; k++) {
        v[k].x *= g; v[k].y *= g; v[k].z *= g; v[k].w *= g;
        __stcs(op + base + (size_t)k * 256, v[k]);
    }
}

// ---------------------------------------------------------------------------
extern "C" void kernel_launch(void* const* d_in, const int* in_sizes, int n_in,
                              void* d_out, int out_size) {
    const float* x  = (const float*)d_in[0];
    const float* w1 = (const float*)d_in[1];
    const float* b1 = (const float*)d_in[2];
    const float* w2 = (const float*)d_in[3];
    const float* b2 = (const float*)d_in[4];
    float* out = (float*)d_out;

    reduce_max_kernel<<<NBC, 512>>>(x);
    mlp_gate_kernel<<<BATCH, 128>>>(w1, b1, w2, b2);
    scale_kernel<<<8192, 256>>>(x, out);
}

// round 13
// speedup vs baseline: 1.0544x; 1.0363x over previous
#include <cuda_runtime.h>
#include <math.h>

#define BATCH 8
#define CHAN 128
#define PLANE 65536          // D*H*W = 4*128*128
#define NBC (BATCH * CHAN)   // 1024

__device__ float g_max[NBC];
__device__ float g_gate[NBC];

// ---------------------------------------------------------------------------
// Kernel 1: per-(b,c) global max. 512 threads/plane, 32 f4/thread in 4 chunks
// of 8 front-batched loads (scale kernel's proven high-MLP pattern).
// DEFAULT cache policy: lines retained in L2 so the scale kernel (reverse
// traversal) can hit the freshest ~126 MB.
// ---------------------------------------------------------------------------
__global__ __launch_bounds__(512) void reduce_max_kernel(const float* __restrict__ x) {
    const int bc = blockIdx.x;
    const int tid = threadIdx.x;
    const float4* p = reinterpret_cast<const float4*>(x) + (size_t)bc * (PLANE / 4);

    float m = -INFINITY;
    #pragma unroll
    for (int ch = 0; ch < 4; ch++) {
        const int base = ch * 4096 + tid;
        float4 v[8];
        #pragma unroll
        for (int k = 0; k < 8; k++)
            v[k] = p[base + k * 512];
        float a0 = -INFINITY, a1 = -INFINITY;
        #pragma unroll
        for (int k = 0; k < 8; k += 2) {
            a0 = fmaxf(a0, fmaxf(fmaxf(v[k].x, v[k].y), fmaxf(v[k].z, v[k].w)));
            a1 = fmaxf(a1, fmaxf(fmaxf(v[k+1].x, v[k+1].y), fmaxf(v[k+1].z, v[k+1].w)));
        }
        m = fmaxf(m, fmaxf(a0, a1));
    }

    #pragma unroll
    for (int off = 16; off > 0; off >>= 1)
        m = fmaxf(m, __shfl_xor_sync(0xffffffffu, m, off));

    __shared__ float sm[16];
    if ((tid & 31) == 0) sm[tid >> 5] = m;
    __syncthreads();
    if (tid < 16) {
        m = sm[tid];
        #pragma unroll
        for (int off = 8; off > 0; off >>= 1)
            m = fmaxf(m, __shfl_xor_sync(0x0000ffffu, m, off));
        if (tid == 0) g_max[bc] = m;
    }
}

// ---------------------------------------------------------------------------
// Kernel 2: full MLP gate, 8 blocks (one per batch) x 128 threads (verified).
// ---------------------------------------------------------------------------
__global__ __launch_bounds__(128) void mlp_gate_kernel(const float* __restrict__ w1,
                                                       const float* __restrict__ b1,
                                                       const float* __restrict__ w2,
                                                       const float* __restrict__ b2) {
    const int b = blockIdx.x;
    const int o = threadIdx.x;

    __shared__ float gp[CHAN];
    __shared__ float hs[CHAN];
    gp[o] = g_max[b * CHAN + o];
    __syncthreads();

    {
        float acc = __ldg(&b1[o]);
        const float4* wrow = reinterpret_cast<const float4*>(w1 + (size_t)o * CHAN);
        #pragma unroll 8
        for (int q = 0; q < CHAN / 4; q++) {
            float4 w = __ldg(wrow + q);
            const int k = q * 4;
            acc = fmaf(gp[k],     w.x, acc);
            acc = fmaf(gp[k + 1], w.y, acc);
            acc = fmaf(gp[k + 2], w.z, acc);
            acc = fmaf(gp[k + 3], w.w, acc);
        }
        hs[o] = fmaxf(acc, 0.0f);
    }
    __syncthreads();

    {
        float acc = __ldg(&b2[o]);
        const float4* wrow = reinterpret_cast<const float4*>(w2 + (size_t)o * CHAN);
        #pragma unroll 8
        for (int q = 0; q < CHAN / 4; q++) {
            float4 w = __ldg(wrow + q);
            const int k = q * 4;
            acc = fmaf(hs[k],     w.x, acc);
            acc = fmaf(hs[k + 1], w.y, acc);
            acc = fmaf(hs[k + 2], w.z, acc);
            acc = fmaf(hs[k + 3], w.w, acc);
        }
        g_gate[b * CHAN + o] = 1.0f / (1.0f + expf(-acc));
    }
}

// ---------------------------------------------------------------------------
// Kernel 3: out = x * gate[bc], REVERSE traversal: block j handles region
// (8191-j), so the first-scheduled blocks read the lines reduce touched most
// recently (still L2-resident). Loads __ldcs (hits allowed, marks evict-
// first after use); stores __stcs (don't evict input with output).
// ---------------------------------------------------------------------------
__global__ __launch_bounds__(256) void scale_kernel(const float* __restrict__ x,
                                                    float* __restrict__ out) {
    const int rb = 8191 - (int)blockIdx.x;       // reversed region index
    const float g = g_gate[rb >> 3];             // 8 regions per (b,c) plane
    const size_t base = (size_t)rb * 2048 + threadIdx.x;
    const float4* xp = reinterpret_cast<const float4*>(x);
    float4* op = reinterpret_cast<float4*>(out);

    float4 v[8];
    #pragma unroll
    for (int k = 0; k < 8; k++)
        v[k] = __ldcs(xp + base + (size_t)k * 256);

    #pragma unroll
    for (int k = 0; k < 8; k++) {
        v[k].x *= g; v[k].y *= g; v[k].z *= g; v[k].w *= g;
        __stcs(op + base + (size_t)k * 256, v[k]);
    }
}

// ---------------------------------------------------------------------------
extern "C" void kernel_launch(void* const* d_in, const int* in_sizes, int n_in,
                              void* d_out, int out_size) {
    const float* x  = (const float*)d_in[0];
    const float* w1 = (const float*)d_in[1];
    const float* b1 = (const float*)d_in[2];
    const float* w2 = (const float*)d_in[3];
    const float* b2 = (const float*)d_in[4];
    float* out = (float*)d_out;

    reduce_max_kernel<<<NBC, 512>>>(x);
    mlp_gate_kernel<<<BATCH, 128>>>(w1, b1, w2, b2);
    scale_kernel<<<8192, 256>>>(x, out);
}